// round 6
// baseline (speedup 1.0000x reference)
#include <cuda_runtime.h>

#define NN 100000
#define EE 1600000
#define DD 64
#define GG 64
#define OUTC 10
#define NB ((NN + 255) / 256)   // 391 scan blocks

// ---- scratch (static device arrays) ----
__device__ int   g_is64;
__device__ int   g_src[EE];
__device__ int   g_dst[EE];
__device__ int   g_batch[NN];
__device__ int   g_deg[NN];
__device__ int   g_cursor[NN];
__device__ int   g_rowstart[NN + 1];
__device__ int   g_bsum[NB];
__device__ int   g_bsum_sc[NB];
__device__ int   g_adj[EE];
__device__ float g_inv_deg[NN];
__device__ float g_h0[(size_t)NN * DD];
__device__ float g_h1[(size_t)NN * DD];
__device__ float g_pool[GG * DD];

// ---------------- dtype detection ----------------
// Reference declares int64 but JAX x64-off + harness policy usually delivers
// int32 ("int32 -> const int*" is the only integer dtype the stub documents).
// Detect at runtime: view edge_index head as int64 pairs; indices < 2^31 mean
// genuine int64 data has all-zero high words. Random int32 indices won't.
__global__ void detect_kernel(const unsigned int* __restrict__ w) {
    int is64 = 1;
    for (int i = 0; i < 32; i++)
        if (w[2 * i + 1] != 0u) { is64 = 0; break; }
    g_is64 = is64;
}

// ---------------- convert indices + zero int scratch ----------------
__global__ void convert_kernel(const void* __restrict__ ei,
                               const void* __restrict__ bat) {
    int i = blockIdx.x * blockDim.x + threadIdx.x;
    int is64 = g_is64;   // uniform branch
    if (i < EE) {
        if (is64) {
            g_src[i] = (int)((const long long*)ei)[i];
            g_dst[i] = (int)((const long long*)ei)[EE + i];
        } else {
            g_src[i] = ((const int*)ei)[i];
            g_dst[i] = ((const int*)ei)[EE + i];
        }
    }
    if (i < NN) {
        g_batch[i] = is64 ? (int)((const long long*)bat)[i]
                          : ((const int*)bat)[i];
        g_deg[i] = 0;
        g_cursor[i] = 0;
    }
}

// ---------------- CSR build ----------------
__global__ void deg_kernel() {
    int e = blockIdx.x * blockDim.x + threadIdx.x;
    if (e < EE) atomicAdd(&g_deg[g_dst[e]], 1);   // int RED.ADD
}

// block-local exclusive scan of g_deg -> g_rowstart, block sums -> g_bsum
__global__ void scan_block_kernel() {
    __shared__ int s[256];
    int tid = threadIdx.x;
    int i = blockIdx.x * 256 + tid;
    int v = (i < NN) ? g_deg[i] : 0;
    s[tid] = v;
    __syncthreads();
    #pragma unroll
    for (int off = 1; off < 256; off <<= 1) {
        int t = (tid >= off) ? s[tid - off] : 0;
        __syncthreads();
        s[tid] += t;
        __syncthreads();
    }
    if (i < NN) g_rowstart[i] = s[tid] - v;   // exclusive
    if (tid == 255) g_bsum[blockIdx.x] = s[255];
}

__global__ void scan_top_kernel() {
    __shared__ int s[512];
    int tid = threadIdx.x;
    int v = (tid < NB) ? g_bsum[tid] : 0;
    s[tid] = v;
    __syncthreads();
    #pragma unroll
    for (int off = 1; off < 512; off <<= 1) {
        int t = (tid >= off) ? s[tid - off] : 0;
        __syncthreads();
        s[tid] += t;
        __syncthreads();
    }
    if (tid < NB) g_bsum_sc[tid] = s[tid] - v;   // exclusive
}

__global__ void scan_add_kernel() {
    int tid = threadIdx.x;
    int i = blockIdx.x * 256 + tid;
    if (i < NN) {
        g_rowstart[i] += g_bsum_sc[blockIdx.x];
        g_inv_deg[i] = 1.0f / (float)max(g_deg[i], 1);
    }
    if (i == 0) g_rowstart[NN] = EE;
}

__global__ void csr_fill_kernel() {
    int e = blockIdx.x * blockDim.x + threadIdx.x;
    if (e < EE) {
        int dst = g_dst[e];
        int pos = atomicAdd(&g_cursor[dst], 1);   // int RED
        g_adj[g_rowstart[dst] + pos] = g_src[e];
    }
}

// ---------------- fused SAGE layer ----------------
// out = relu( inv_deg * (sum_{s in N(n)} hin[s]) @ Wl + bl + hin[n] @ Wr )
// 256 threads = 4 sub-groups x 64 cols; 64 nodes per block.
// sel: 0: x -> h0 ; 1: h0 -> h1 ; 2: h1 -> h0
__global__ void sage_fused_kernel(int sel, const float* __restrict__ x,
                                  const float* __restrict__ Wl,
                                  const float* __restrict__ bl,
                                  const float* __restrict__ Wr) {
    __shared__ float sWl[DD * DD];
    __shared__ float sWr[DD * DD];
    __shared__ float sb[DD];
    __shared__ float sagg[4][DD];
    __shared__ float shr[4][DD];

    const float* hin  = (sel == 0) ? x    : ((sel == 1) ? g_h0 : g_h1);
    float*       hout = (sel == 0) ? g_h0 : ((sel == 1) ? g_h1 : g_h0);

    int tid = threadIdx.x;
    for (int i = tid; i < DD * DD; i += 256) { sWl[i] = Wl[i]; sWr[i] = Wr[i]; }
    if (tid < DD) sb[tid] = bl[tid];
    __syncthreads();

    int col = tid & 63;
    int sub = tid >> 6;           // 0..3
    const int NPB = 64;
    int base = blockIdx.x * NPB;

    for (int nn = sub; nn < NPB; nn += 4) {
        int node = base + nn;
        float aggc = 0.f, hc = 0.f, sc = 0.f;
        if (node < NN) {
            int rs = g_rowstart[node];
            int re = g_rowstart[node + 1];
            for (int e = rs; e < re; e++) {
                int s = g_adj[e];                       // uniform across sub
                aggc += hin[(size_t)s * DD + col];      // coalesced row read
            }
            sc = g_inv_deg[node];
            hc = hin[(size_t)node * DD + col];
        }
        sagg[sub][col] = aggc * sc;
        shr[sub][col]  = hc;
        __syncthreads();
        float accA = 0.f, accB = 0.f;
        #pragma unroll
        for (int k = 0; k < DD; k++) {
            accA = fmaf(sagg[sub][k], sWl[k * DD + col], accA);
            accB = fmaf(shr[sub][k],  sWr[k * DD + col], accB);
        }
        if (node < NN)
            hout[(size_t)node * DD + col] = fmaxf(accA + accB + sb[col], 0.f);
        __syncthreads();
    }
}

// ---------------- global mean pool (batch sorted -> binary search ranges) -----
__global__ void pool_kernel() {
    int g = blockIdx.x;          // 64 blocks
    int col = threadIdx.x;       // 64 threads
    int a = 0, b = NN;
    while (a < b) { int m = (a + b) >> 1; if (g_batch[m] < g) a = m + 1; else b = m; }
    int start = a;
    b = NN;
    while (a < b) { int m = (a + b) >> 1; if (g_batch[m] < g + 1) a = m + 1; else b = m; }
    int end = a;
    float acc = 0.f;
    for (int n = start; n < end; n++) acc += g_h0[(size_t)n * DD + col];
    g_pool[g * DD + col] = acc / fmaxf((float)(end - start), 1.f);
}

// ---------------- final MLP ----------------
__global__ void mlp_kernel(const float* __restrict__ l0W,
                           const float* __restrict__ l0b,
                           const float* __restrict__ outW,
                           const float* __restrict__ outb,
                           float* __restrict__ out) {
    __shared__ float sg[DD];
    __shared__ float sh[DD];
    int gi = blockIdx.x, t = threadIdx.x;
    sg[t] = g_pool[gi * DD + t];
    __syncthreads();
    float acc = l0b[t];
    #pragma unroll
    for (int k = 0; k < DD; k++) acc = fmaf(sg[k], l0W[k * DD + t], acc);
    sh[t] = fmaxf(acc, 0.f);
    __syncthreads();
    if (t < OUTC) {
        float a = outb[t];
        #pragma unroll
        for (int k = 0; k < DD; k++) a = fmaf(sh[k], outW[k * OUTC + t], a);
        out[gi * OUTC + t] = a;
    }
}

extern "C" void kernel_launch(void* const* d_in, const int* in_sizes, int n_in,
                              void* d_out, int out_size) {
    const float* x    = (const float*)d_in[0];
    const void*  ei   = d_in[1];
    const void*  bat  = d_in[2];
    const float* c_Wl[3] = { (const float*)d_in[3], (const float*)d_in[6], (const float*)d_in[9]  };
    const float* c_bl[3] = { (const float*)d_in[4], (const float*)d_in[7], (const float*)d_in[10] };
    const float* c_Wr[3] = { (const float*)d_in[5], (const float*)d_in[8], (const float*)d_in[11] };
    const float* l0W  = (const float*)d_in[12];
    const float* l0b  = (const float*)d_in[13];
    const float* outW = (const float*)d_in[14];
    const float* outb = (const float*)d_in[15];
    float* out = (float*)d_out;

    // ---- dtype detect + index conversion ----
    detect_kernel<<<1, 1>>>((const unsigned int*)ei);
    convert_kernel<<<(EE + 255) / 256, 256>>>(ei, bat);

    // ---- CSR build ----
    deg_kernel<<<(EE + 255) / 256, 256>>>();
    scan_block_kernel<<<NB, 256>>>();
    scan_top_kernel<<<1, 512>>>();
    scan_add_kernel<<<NB, 256>>>();
    csr_fill_kernel<<<(EE + 255) / 256, 256>>>();

    // ---- 3 fused SAGE layers ----
    const int sage_blocks = (NN + 63) / 64;
    sage_fused_kernel<<<sage_blocks, 256>>>(0, x, c_Wl[0], c_bl[0], c_Wr[0]);
    sage_fused_kernel<<<sage_blocks, 256>>>(1, x, c_Wl[1], c_bl[1], c_Wr[1]);
    sage_fused_kernel<<<sage_blocks, 256>>>(2, x, c_Wl[2], c_bl[2], c_Wr[2]);

    // ---- pooling + MLP ----
    pool_kernel<<<GG, DD>>>();
    mlp_kernel<<<GG, DD>>>(l0W, l0b, outW, outb, out);
}